// round 11
// baseline (speedup 1.0000x reference)
#include <cuda_runtime.h>
#include <cuda_bf16.h>
#include <math.h>
#include <stdint.h>

#define NN 50000
#define NE 800000
#define HID 128
#define HID2 256
#define STEPS 12
#define DTC 0.5f
#define NTILES 391   // ceil(NN/128)
#define GTHREADS 512

// ---- A-image layout: per 128-row tile: 128 rows x 16 units;
// unit = 8 bf16 cols stored as 16B hi || 16B lo (32B). phys = ku ^ (r&7).
// Tile image = 65536 B.
__device__ __forceinline__ uint32_t img_off(int r, int ku) {
    return (((uint32_t)r << 4) + ((uint32_t)ku ^ (r & 7))) * 32u;
}

// ================= scratch =================
__device__ uint8_t g_aggimg[(size_t)NTILES * 65536];   // 25.6 MB (hi/lo image)
__device__ float   g_invdeg[NN];
__device__ int     g_degi[NN];
__device__ int     g_rowptr[NN + 1];
__device__ int     g_cursor[NN];
__device__ int     g_srcs[NE];
// weight images hi block then lo block ([N][K] units, 16B-unit XOR swizzle)
__device__ uint8_t g_Wimg_in[2 * 128 * 128 * 2];   //  64 KB
__device__ uint8_t g_Wimg1[2 * 256 * 128 * 2];     // 128 KB
__device__ uint8_t g_Wimg2[2 * 128 * 256 * 2];     // 128 KB

// ================= fast math =================
__device__ __forceinline__ float fast_tanh(float x) {
    float e = __expf(2.0f * x);
    return 1.0f - __fdividef(2.0f, e + 1.0f);
}

// ================= CSR build =================
__global__ void k_zero_degi() {
    int i = blockIdx.x * blockDim.x + threadIdx.x;
    if (i < NN) g_degi[i] = 0;
}
__global__ void k_hist(const int* __restrict__ ei) {
    int e = blockIdx.x * blockDim.x + threadIdx.x;
    if (e < NE) atomicAdd(&g_degi[ei[NE + e]], 1);
}
__global__ void k_scan() {
    __shared__ int part[1024];
    const int C = (NN + 1023) / 1024;
    int t = threadIdx.x;
    int beg = t * C, end = min(beg + C, NN);
    int s = 0;
    for (int i = beg; i < end; i++) s += g_degi[i];
    part[t] = s;
    __syncthreads();
    for (int off = 1; off < 1024; off <<= 1) {
        int v = (t >= off) ? part[t - off] : 0;
        __syncthreads();
        part[t] += v;
        __syncthreads();
    }
    int run = part[t] - s;
    for (int i = beg; i < end; i++) {
        int d = g_degi[i];
        g_rowptr[i] = run;
        g_cursor[i] = run;
        g_invdeg[i] = 1.0f / (float)max(d, 1);
        run += d;
    }
    if (t == 1023) g_rowptr[NN] = NE;
}
__global__ void k_scatter(const int* __restrict__ ei) {
    int e = blockIdx.x * blockDim.x + threadIdx.x;
    if (e < NE) {
        int dst = ei[NE + e];
        int p = atomicAdd(&g_cursor[dst], 1);
        g_srcs[p] = ei[e];
    }
}

// ================= bf16 split helpers =================
__device__ __forceinline__ void split4(float v0, float v1, float v2, float v3,
                                       ushort4& H, ushort4& L) {
    __nv_bfloat16 h0 = __float2bfloat16(v0), h1 = __float2bfloat16(v1);
    __nv_bfloat16 h2 = __float2bfloat16(v2), h3 = __float2bfloat16(v3);
    H.x = __bfloat16_as_ushort(h0); H.y = __bfloat16_as_ushort(h1);
    H.z = __bfloat16_as_ushort(h2); H.w = __bfloat16_as_ushort(h3);
    L.x = __bfloat16_as_ushort(__float2bfloat16(v0 - __bfloat162float(h0)));
    L.y = __bfloat16_as_ushort(__float2bfloat16(v1 - __bfloat162float(h1)));
    L.z = __bfloat16_as_ushort(__float2bfloat16(v2 - __bfloat162float(h2)));
    L.w = __bfloat16_as_ushort(__float2bfloat16(v3 - __bfloat162float(h3)));
}

// ================= aggregation: writes hi/lo image =================
__global__ void k_aggregate(const float* __restrict__ h, uint8_t* __restrict__ img) {
    int node = (blockIdx.x * blockDim.x + threadIdx.x) >> 5;
    int lane = threadIdx.x & 31;
    if (node >= NN) return;
    int beg = g_rowptr[node], end = g_rowptr[node + 1];
    float4 a0 = make_float4(0.f, 0.f, 0.f, 0.f);
    float4 a1 = a0, a2 = a0, a3 = a0;
    int i = beg;
    for (; i + 3 < end; i += 4) {
        int s0 = g_srcs[i], s1 = g_srcs[i + 1], s2 = g_srcs[i + 2], s3 = g_srcs[i + 3];
        float4 v0 = *(const float4*)&h[(size_t)s0 * HID + lane * 4];
        float4 v1 = *(const float4*)&h[(size_t)s1 * HID + lane * 4];
        float4 v2 = *(const float4*)&h[(size_t)s2 * HID + lane * 4];
        float4 v3 = *(const float4*)&h[(size_t)s3 * HID + lane * 4];
        a0.x += v0.x; a0.y += v0.y; a0.z += v0.z; a0.w += v0.w;
        a1.x += v1.x; a1.y += v1.y; a1.z += v1.z; a1.w += v1.w;
        a2.x += v2.x; a2.y += v2.y; a2.z += v2.z; a2.w += v2.w;
        a3.x += v3.x; a3.y += v3.y; a3.z += v3.z; a3.w += v3.w;
    }
    for (; i < end; i++) {
        float4 v0 = *(const float4*)&h[(size_t)g_srcs[i] * HID + lane * 4];
        a0.x += v0.x; a0.y += v0.y; a0.z += v0.z; a0.w += v0.w;
    }
    float inv = g_invdeg[node];
    float m0 = (a0.x + a1.x + a2.x + a3.x) * inv;
    float m1 = (a0.y + a1.y + a2.y + a3.y) * inv;
    float m2 = (a0.z + a1.z + a2.z + a3.z) * inv;
    float m3 = (a0.w + a1.w + a2.w + a3.w) * inv;
    ushort4 H, L;
    split4(m0, m1, m2, m3, H, L);
    int tile = node >> 7, r = node & 127;
    uint8_t* base = img + (size_t)tile * 65536 + img_off(r, lane >> 1) + (lane & 1) * 8;
    *(ushort4*)base = H;
    *(ushort4*)(base + 16) = L;
}

// ================= weight image prep (hi + lo) =================
__global__ void k_prepw(const float* __restrict__ W, uint8_t* __restrict__ img,
                        int K, int NOUT) {
    int idx = blockIdx.x * blockDim.x + threadIdx.x;
    if (idx >= K * NOUT) return;
    int k = idx / NOUT, n = idx % NOUT;
    float v = W[idx];
    __nv_bfloat16 hi = __float2bfloat16(v);
    __nv_bfloat16 lo = __float2bfloat16(v - __bfloat162float(hi));
    int SUW = K >> 3;
    size_t unit = (size_t)n * SUW + ((k >> 3) ^ (n & 7));
    size_t byteo = unit * 16 + (size_t)(k & 7) * 2;
    *(__nv_bfloat16*)(img + byteo) = hi;
    *(__nv_bfloat16*)(img + (size_t)NOUT * K * 2 + byteo) = lo;
}

// ================= mma.sync / cp.async helpers =================
__device__ __forceinline__ uint32_t smem_u32(const void* p) {
    uint32_t a;
    asm("{ .reg .u64 t; cvta.to.shared.u64 t, %1; cvt.u32.u64 %0, t; }" : "=r"(a) : "l"(p));
    return a;
}
__device__ __forceinline__ void cp16(uint32_t dst, const void* src) {
    asm volatile("cp.async.cg.shared.global [%0], [%1], 16;" :: "r"(dst), "l"(src));
}
__device__ __forceinline__ void cp_commit() {
    asm volatile("cp.async.commit_group;");
}
__device__ __forceinline__ void cp_wait_all() {
    asm volatile("cp.async.wait_group 0;");
}
__device__ __forceinline__ void ldmx4(uint32_t* r, uint32_t addr) {
    asm volatile("ldmatrix.sync.aligned.m8n8.x4.shared.b16 {%0,%1,%2,%3}, [%4];"
                 : "=r"(r[0]), "=r"(r[1]), "=r"(r[2]), "=r"(r[3]) : "r"(addr));
}
__device__ __forceinline__ void mma16816(float* c, const uint32_t* a, uint32_t b0, uint32_t b1) {
    asm volatile(
        "mma.sync.aligned.m16n8k16.row.col.f32.bf16.bf16.f32 "
        "{%0,%1,%2,%3}, {%4,%5,%6,%7}, {%8,%9}, {%0,%1,%2,%3};"
        : "+f"(c[0]), "+f"(c[1]), "+f"(c[2]), "+f"(c[3])
        : "r"(a[0]), "r"(a[1]), "r"(a[2]), "r"(a[3]), "r"(b0), "r"(b1));
}

// ================= gemm0: h = tanh(gat @ W_in + b_in), 3-term split ======
// A from fp32 gmem (convert in-kernel), W hi/lo in smem. 512 threads, 4x4 warps.
__global__ void __launch_bounds__(GTHREADS, 1) k_gemm0(
    const float* __restrict__ X, const uint8_t* __restrict__ Wimg,
    const float* __restrict__ Bb, float* __restrict__ OUT, int ntiles)
{
    constexpr int K = 128, NOUT = 128, SUW = 16, AUNITS = 128 * 16;
    extern __shared__ char smem[];
    uint4* Ah = (uint4*)smem;
    uint4* Al = Ah + AUNITS;
    uint4* Wh = Al + AUNITS;
    const uint32_t ah_b = smem_u32(Ah);
    const uint32_t al_b = smem_u32(Al);
    const uint32_t wh_b = smem_u32(Wh);
    const uint32_t wl_b = wh_b + NOUT * SUW * 16;

    const int tid = threadIdx.x;
    const int lane = tid & 31;
    const int wid = tid >> 5;
    const int wm = wid & 3;
    const int wn = wid >> 2;
    const int r8 = lane & 7;
    const int quad = lane >> 3;
    const int g = lane >> 2;
    const int tq = lane & 3;

    for (int i = tid; i < 2 * NOUT * SUW; i += GTHREADS)
        cp16(wh_b + i * 16, (const uint4*)Wimg + i);
    cp_commit();

    for (int tile = blockIdx.x; tile < ntiles; tile += gridDim.x) {
        const int row0 = tile * 128;
        __syncthreads();
        #pragma unroll 1
        for (int u = tid; u < AUNITS; u += GTHREADS) {
            int r = u >> 4, ku = u & 15;
            int gr = row0 + r;
            float4 v0 = make_float4(0.f, 0.f, 0.f, 0.f), v1 = v0;
            if (gr < NN) {
                const float* xp = &X[(size_t)gr * K + ku * 8];
                v0 = *(const float4*)xp;
                v1 = *(const float4*)(xp + 4);
            }
            uint32_t a16 = (((uint32_t)r << 4) + ((uint32_t)ku ^ (r & 7))) * 16;
            ushort4 H, L;
            split4(v0.x, v0.y, v0.z, v0.w, H, L);
            *(ushort4*)((char*)Ah + a16) = H;
            *(ushort4*)((char*)Al + a16) = L;
            split4(v1.x, v1.y, v1.z, v1.w, H, L);
            *(ushort4*)((char*)Ah + a16 + 8) = H;
            *(ushort4*)((char*)Al + a16 + 8) = L;
        }
        cp_wait_all();
        __syncthreads();

        float acc[2][4][4];
        #pragma unroll
        for (int a = 0; a < 2; a++)
            #pragma unroll
            for (int b = 0; b < 4; b++)
                #pragma unroll
                for (int c = 0; c < 4; c++) acc[a][b][c] = 0.f;

        #pragma unroll
        for (int ks = 0; ks < 8; ks++) {
            uint32_t a_hi[2][4], a_lo[2][4];
            #pragma unroll
            for (int mt = 0; mt < 2; mt++) {
                int row = wm * 32 + mt * 16 + r8 + (quad & 1) * 8;
                int ku = 2 * ks + (quad >> 1);
                uint32_t off = ((row << 4) + (ku ^ (row & 7))) * 16;
                ldmx4(a_hi[mt], ah_b + off);
                ldmx4(a_lo[mt], al_b + off);
            }
            #pragma unroll
            for (int nt2 = 0; nt2 < 2; nt2++) {
                int nrow = wn * 32 + nt2 * 16 + r8 + (quad >> 1) * 8;
                int ku = 2 * ks + (quad & 1);
                uint32_t off = ((uint32_t)nrow * SUW + (ku ^ (nrow & 7))) * 16;
                uint32_t bh[4], bl[4];
                ldmx4(bh, wh_b + off);
                ldmx4(bl, wl_b + off);
                #pragma unroll
                for (int mt = 0; mt < 2; mt++) {
                    mma16816(acc[mt][2 * nt2 + 0], a_hi[mt], bh[0], bh[1]);
                    mma16816(acc[mt][2 * nt2 + 0], a_lo[mt], bh[0], bh[1]);
                    mma16816(acc[mt][2 * nt2 + 0], a_hi[mt], bl[0], bl[1]);
                    mma16816(acc[mt][2 * nt2 + 1], a_hi[mt], bh[2], bh[3]);
                    mma16816(acc[mt][2 * nt2 + 1], a_lo[mt], bh[2], bh[3]);
                    mma16816(acc[mt][2 * nt2 + 1], a_hi[mt], bl[2], bl[3]);
                }
            }
        }

        #pragma unroll
        for (int mt = 0; mt < 2; mt++) {
            int rbase = row0 + wm * 32 + mt * 16 + g;
            #pragma unroll
            for (int nt = 0; nt < 4; nt++) {
                int col = wn * 32 + nt * 8 + 2 * tq;
                float2 bb = *(const float2*)&Bb[col];
                #pragma unroll
                for (int half = 0; half < 2; half++) {
                    int row = rbase + half * 8;
                    if (row >= NN) continue;
                    float2 o;
                    o.x = fast_tanh(acc[mt][nt][2 * half + 0] + bb.x);
                    o.y = fast_tanh(acc[mt][nt][2 * half + 1] + bb.y);
                    *(float2*)&OUT[(size_t)row * NOUT + col] = o;
                }
            }
        }
    }
}

// ================= fused MLP: x1 = gelu(agg@W1+b1); h += (tanh(x1@W2+b2)-decay*h)*dt
// SMEM: [Wbuf 128KB][Abuf 64KB]. W swapped W1<->W2 per phase via cp.async;
// x1 staged in Abuf (bf16 hi/lo image) after GEMM1 consumes A.
__global__ void __launch_bounds__(GTHREADS, 1) k_mlp(
    const uint8_t* __restrict__ aggimg,
    const uint8_t* __restrict__ W1img, const float* __restrict__ b1,
    const uint8_t* __restrict__ W2img, const float* __restrict__ b2,
    float* __restrict__ h, const float* __restrict__ clr, int ntiles)
{
    extern __shared__ char smem[];
    uint8_t* Abuf = (uint8_t*)smem + 131072;
    const uint32_t wb = smem_u32(smem);
    const uint32_t ab = wb + 131072;

    const int tid = threadIdx.x;
    const int lane = tid & 31;
    const int wid = tid >> 5;
    const int wm = wid & 3;
    const int wn = wid >> 2;
    const int r8 = lane & 7;
    const int quad = lane >> 3;
    const int g = lane >> 2;
    const int tq = lane & 3;

    const float decay = fmaxf(clr[0], 0.f);

    // initial: W1 + A(tile0)
    {
        for (int i = tid; i < 8192; i += GTHREADS)
            cp16(wb + i * 16, W1img + (size_t)i * 16);
        const uint8_t* asrc = aggimg + (size_t)blockIdx.x * 65536;
        for (int i = tid; i < 4096; i += GTHREADS)
            cp16(ab + i * 16, asrc + (size_t)i * 16);
        cp_commit();
    }

    for (int tile = blockIdx.x; tile < ntiles; tile += gridDim.x) {
        const int row0 = tile * 128;
        cp_wait_all();
        __syncthreads();

        // ---------- GEMM1: acc1 = agg @ W1 (3-term) ----------
        float acc1[2][2][4][4];
        #pragma unroll
        for (int nb = 0; nb < 2; nb++)
            #pragma unroll
            for (int a = 0; a < 2; a++)
                #pragma unroll
                for (int b = 0; b < 4; b++)
                    #pragma unroll
                    for (int c = 0; c < 4; c++) acc1[nb][a][b][c] = 0.f;

        #pragma unroll
        for (int ks = 0; ks < 8; ks++) {
            uint32_t a_hi[2][4], a_lo[2][4];
            #pragma unroll
            for (int mt = 0; mt < 2; mt++) {
                int row = wm * 32 + mt * 16 + r8 + (quad & 1) * 8;
                int ku = 2 * ks + (quad >> 1);
                uint32_t off = ab + (((uint32_t)row << 4) + (ku ^ (row & 7))) * 32;
                ldmx4(a_hi[mt], off);
                ldmx4(a_lo[mt], off + 16);
            }
            #pragma unroll
            for (int nb = 0; nb < 2; nb++) {
                #pragma unroll
                for (int nt2 = 0; nt2 < 2; nt2++) {
                    int nrow = nb * 128 + wn * 32 + nt2 * 16 + r8 + (quad >> 1) * 8;
                    int ku = 2 * ks + (quad & 1);
                    uint32_t off = ((uint32_t)nrow * 16 + (ku ^ (nrow & 7))) * 16;
                    uint32_t bh[4], bl[4];
                    ldmx4(bh, wb + off);
                    ldmx4(bl, wb + 65536 + off);
                    #pragma unroll
                    for (int mt = 0; mt < 2; mt++) {
                        mma16816(acc1[nb][mt][2 * nt2 + 0], a_hi[mt], bh[0], bh[1]);
                        mma16816(acc1[nb][mt][2 * nt2 + 0], a_lo[mt], bh[0], bh[1]);
                        mma16816(acc1[nb][mt][2 * nt2 + 0], a_hi[mt], bl[0], bl[1]);
                        mma16816(acc1[nb][mt][2 * nt2 + 1], a_hi[mt], bh[2], bh[3]);
                        mma16816(acc1[nb][mt][2 * nt2 + 1], a_lo[mt], bh[2], bh[3]);
                        mma16816(acc1[nb][mt][2 * nt2 + 1], a_hi[mt], bl[2], bl[3]);
                    }
                }
            }
        }
        __syncthreads();   // all reads of Abuf(W1 too) done

        // swap W -> W2 (overlaps x1 staging stores)
        for (int i = tid; i < 8192; i += GTHREADS)
            cp16(wb + i * 16, W2img + (size_t)i * 16);
        cp_commit();

        float acc2[2][4][4];
        #pragma unroll
        for (int a = 0; a < 2; a++)
            #pragma unroll
            for (int b = 0; b < 4; b++)
                #pragma unroll
                for (int c = 0; c < 4; c++) acc2[a][b][c] = 0.f;

        // ---------- per-half: stage x1_nb into Abuf, GEMM2 chunk nb ----------
        #pragma unroll 1
        for (int nb = 0; nb < 2; nb++) {
            // stage x1[:, nb*128:(nb+1)*128] as bf16 hi/lo image
            const float cgel = 0.7071067811865475f;
            #pragma unroll
            for (int mt = 0; mt < 2; mt++) {
                #pragma unroll
                for (int nt = 0; nt < 4; nt++) {
                    int cl = wn * 32 + nt * 8 + 2 * tq;
                    float2 bb = *(const float2*)&b1[nb * 128 + cl];
                    #pragma unroll
                    for (int half = 0; half < 2; half++) {
                        int rl = wm * 32 + mt * 16 + g + half * 8;
                        float x0 = acc1[nb][mt][nt][2 * half + 0] + bb.x;
                        float x1 = acc1[nb][mt][nt][2 * half + 1] + bb.y;
                        float g0 = 0.5f * x0 * (1.f + erff(x0 * cgel));
                        float g1 = 0.5f * x1 * (1.f + erff(x1 * cgel));
                        __nv_bfloat16 h0 = __float2bfloat16(g0);
                        __nv_bfloat16 h1 = __float2bfloat16(g1);
                        uint32_t hiw = ((uint32_t)__bfloat16_as_ushort(h1) << 16)
                                     | __bfloat16_as_ushort(h0);
                        uint32_t low = ((uint32_t)__bfloat16_as_ushort(
                                           __float2bfloat16(g1 - __bfloat162float(h1))) << 16)
                                     | __bfloat16_as_ushort(
                                           __float2bfloat16(g0 - __bfloat162float(h0)));
                        uint32_t off = img_off(rl, cl >> 3) + (cl & 7) * 2;
                        *(uint32_t*)(Abuf + off) = hiw;
                        *(uint32_t*)(Abuf + off + 16) = low;
                    }
                }
            }
            if (nb == 0) cp_wait_all();   // W2 in place before chunk0 LDSM
            __syncthreads();

            // GEMM2 chunk nb: acc2 += x1_nb @ W2[nb*128:(nb+1)*128, :]
            #pragma unroll
            for (int ks = 0; ks < 8; ks++) {
                uint32_t a_hi[2][4], a_lo[2][4];
                #pragma unroll
                for (int mt = 0; mt < 2; mt++) {
                    int row = wm * 32 + mt * 16 + r8 + (quad & 1) * 8;
                    int ku = 2 * ks + (quad >> 1);
                    uint32_t off = ab + (((uint32_t)row << 4) + (ku ^ (row & 7))) * 32;
                    ldmx4(a_hi[mt], off);
                    ldmx4(a_lo[mt], off + 16);
                }
                #pragma unroll
                for (int nt2 = 0; nt2 < 2; nt2++) {
                    int nrow = wn * 32 + nt2 * 16 + r8 + (quad >> 1) * 8;
                    int ku = nb * 16 + 2 * ks + (quad & 1);
                    uint32_t off = ((uint32_t)nrow * 32 + (ku ^ (nrow & 7))) * 16;
                    uint32_t bh[4], bl[4];
                    ldmx4(bh, wb + off);
                    ldmx4(bl, wb + 65536 + off);
                    #pragma unroll
                    for (int mt = 0; mt < 2; mt++) {
                        mma16816(acc2[mt][2 * nt2 + 0], a_hi[mt], bh[0], bh[1]);
                        mma16816(acc2[mt][2 * nt2 + 0], a_lo[mt], bh[0], bh[1]);
                        mma16816(acc2[mt][2 * nt2 + 0], a_hi[mt], bl[0], bl[1]);
                        mma16816(acc2[mt][2 * nt2 + 1], a_hi[mt], bh[2], bh[3]);
                        mma16816(acc2[mt][2 * nt2 + 1], a_lo[mt], bh[2], bh[3]);
                        mma16816(acc2[mt][2 * nt2 + 1], a_hi[mt], bl[2], bl[3]);
                    }
                }
            }
            __syncthreads();   // Abuf reads done before restage / prefetch
        }

        // prefetch next tile A + restore W1 (overlaps epilogue)
        {
            int nxt = tile + gridDim.x;
            const uint8_t* asrc = aggimg
                + (size_t)((nxt < ntiles) ? nxt : tile) * 65536;
            for (int i = tid; i < 4096; i += GTHREADS)
                cp16(ab + i * 16, asrc + (size_t)i * 16);
            for (int i = tid; i < 8192; i += GTHREADS)
                cp16(wb + i * 16, W1img + (size_t)i * 16);
            cp_commit();
        }

        // ---------- epilogue: Euler update of h ----------
        #pragma unroll
        for (int mt = 0; mt < 2; mt++) {
            int rbase = row0 + wm * 32 + mt * 16 + g;
            #pragma unroll
            for (int nt = 0; nt < 4; nt++) {
                int col = wn * 32 + nt * 8 + 2 * tq;
                float2 bb = *(const float2*)&b2[col];
                #pragma unroll
                for (int half = 0; half < 2; half++) {
                    int row = rbase + half * 8;
                    if (row >= NN) continue;
                    float x0 = acc2[mt][nt][2 * half + 0] + bb.x;
                    float x1 = acc2[mt][nt][2 * half + 1] + bb.y;
                    float2 hv = *(const float2*)&h[(size_t)row * HID + col];
                    float2 o;
                    o.x = hv.x + (fast_tanh(x0) - decay * hv.x) * DTC;
                    o.y = hv.y + (fast_tanh(x1) - decay * hv.y) * DTC;
                    *(float2*)&h[(size_t)row * HID + col] = o;
                }
            }
        }
    }
    cp_wait_all();     // drain trailing prefetch before exit
    __syncthreads();
}

// ================= launch =================
extern "C" void kernel_launch(void* const* d_in, const int* in_sizes, int n_in,
                              void* d_out, int out_size) {
    const float* gat  = (const float*)d_in[0];
    const int*   ei   = (const int*)d_in[1];
    const float* W_in = (const float*)d_in[2];
    const float* b_in = (const float*)d_in[3];
    const float* W1   = (const float*)d_in[4];
    const float* b1   = (const float*)d_in[5];
    const float* W2   = (const float*)d_in[6];
    const float* b2   = (const float*)d_in[7];
    const float* clr  = (const float*)d_in[8];
    float* h = (float*)d_out;

    uint8_t *aggimg = nullptr, *wi_in = nullptr, *wi_1 = nullptr, *wi_2 = nullptr;
    cudaGetSymbolAddress((void**)&aggimg, g_aggimg);
    cudaGetSymbolAddress((void**)&wi_in, g_Wimg_in);
    cudaGetSymbolAddress((void**)&wi_1, g_Wimg1);
    cudaGetSymbolAddress((void**)&wi_2, g_Wimg2);

    int sms = 148;
    cudaDeviceGetAttribute(&sms, cudaDevAttrMultiProcessorCount, 0);

    const int SM_G0  = 65536 + 65536;     // 128 KB (A hi/lo + W hi/lo)
    const int SM_MLP = 131072 + 65536;    // 192 KB (W region + A/x1 stage)
    cudaFuncSetAttribute(k_gemm0, cudaFuncAttributeMaxDynamicSharedMemorySize, SM_G0);
    cudaFuncSetAttribute(k_mlp,   cudaFuncAttributeMaxDynamicSharedMemorySize, SM_MLP);

    const int ntiles = NTILES;
    const int grid = (ntiles < sms) ? ntiles : sms;

    // gemm0 at launch index 3 (profiled slot)
    k_prepw<<<(128 * 128 + 255) / 256, 256>>>(W_in, wi_in, 128, 128);       // 0
    k_zero_degi<<<(NN + 255) / 256, 256>>>();                               // 1
    k_hist<<<(NE + 255) / 256, 256>>>(ei);                                  // 2
    k_gemm0<<<grid, GTHREADS, SM_G0>>>(gat, wi_in, b_in, h, ntiles);        // 3
    k_scan<<<1, 1024>>>();                                                  // 4
    k_scatter<<<(NE + 255) / 256, 256>>>(ei);                               // 5
    k_prepw<<<(128 * 256 + 255) / 256, 256>>>(W1, wi_1, 128, 256);          // 6
    k_prepw<<<(256 * 128 + 255) / 256, 256>>>(W2, wi_2, 256, 128);          // 7

    const int agg_blocks = (NN * 32 + 255) / 256;
    for (int s = 0; s < STEPS; s++) {
        k_aggregate<<<agg_blocks, 256>>>(h, aggimg);
        k_mlp<<<grid, GTHREADS, SM_MLP>>>(aggimg, wi_1, b1, wi_2, b2, h, clr, ntiles);
    }
}

// round 12
// speedup vs baseline: 1.6090x; 1.6090x over previous
#include <cuda_runtime.h>
#include <cuda_fp16.h>
#include <math.h>
#include <stdint.h>

#define NN 50000
#define NE 800000
#define HID 128
#define HID2 256
#define STEPS 12
#define DTC 0.5f
#define NTILES 391   // ceil(NN/128)
#define GTHREADS 512

// ---- A-image layout (hi-only fp16): per 128-row tile, per 128-K chunk:
// 128 rows x 16 units; unit = 8 fp16 cols = 16B. phys unit = ku ^ (r & 7).
// Chunk = 32768 B.
__device__ __forceinline__ uint32_t img_off(int r, int ku) {
    return (((uint32_t)r << 4) + ((uint32_t)ku ^ (r & 7))) * 16u;
}

// ================= scratch =================
__device__ uint8_t g_aggimg[(size_t)NTILES * 32768];        // 12.8 MB
__device__ uint8_t g_x1img[(size_t)NTILES * 2 * 32768];     // 25.6 MB
__device__ float   g_invdeg[NN];
__device__ int     g_degi[NN];
__device__ int     g_rowptr[NN + 1];
__device__ int     g_cursor[NN];
__device__ int     g_srcs[NE];
// weight images keep hi+lo fp16 planes ([N][K], 16B-unit XOR swizzle)
__device__ uint8_t g_Wimg_in[2 * 128 * 128 * 2];
__device__ uint8_t g_Wimg1[2 * 256 * 128 * 2];
__device__ uint8_t g_Wimg2[2 * 128 * 256 * 2];

// ================= fast math =================
__device__ __forceinline__ float fast_tanh(float x) {
    float e = __expf(2.0f * x);
    return 1.0f - __fdividef(2.0f, e + 1.0f);
}

// ================= CSR build =================
__global__ void k_zero_degi() {
    int i = blockIdx.x * blockDim.x + threadIdx.x;
    if (i < NN) g_degi[i] = 0;
}
__global__ void k_hist(const int* __restrict__ ei) {
    int e = blockIdx.x * blockDim.x + threadIdx.x;
    if (e < NE) atomicAdd(&g_degi[ei[NE + e]], 1);
}
__global__ void k_scan() {
    __shared__ int part[1024];
    const int C = (NN + 1023) / 1024;
    int t = threadIdx.x;
    int beg = t * C, end = min(beg + C, NN);
    int s = 0;
    for (int i = beg; i < end; i++) s += g_degi[i];
    part[t] = s;
    __syncthreads();
    for (int off = 1; off < 1024; off <<= 1) {
        int v = (t >= off) ? part[t - off] : 0;
        __syncthreads();
        part[t] += v;
        __syncthreads();
    }
    int run = part[t] - s;
    for (int i = beg; i < end; i++) {
        int d = g_degi[i];
        g_rowptr[i] = run;
        g_cursor[i] = run;
        g_invdeg[i] = 1.0f / (float)max(d, 1);
        run += d;
    }
    if (t == 1023) g_rowptr[NN] = NE;
}
__global__ void k_scatter(const int* __restrict__ ei) {
    int e = blockIdx.x * blockDim.x + threadIdx.x;
    if (e < NE) {
        int dst = ei[NE + e];
        int p = atomicAdd(&g_cursor[dst], 1);
        g_srcs[p] = ei[e];
    }
}

// ================= aggregation: writes hi-only fp16 image =================
__global__ void k_aggregate(const float* __restrict__ h, uint8_t* __restrict__ img) {
    int node = (blockIdx.x * blockDim.x + threadIdx.x) >> 5;
    int lane = threadIdx.x & 31;
    if (node >= NN) return;
    int beg = g_rowptr[node], end = g_rowptr[node + 1];
    float4 a0 = make_float4(0.f, 0.f, 0.f, 0.f);
    float4 a1 = a0, a2 = a0, a3 = a0;
    int i = beg;
    for (; i + 3 < end; i += 4) {
        int s0 = g_srcs[i], s1 = g_srcs[i + 1], s2 = g_srcs[i + 2], s3 = g_srcs[i + 3];
        float4 v0 = *(const float4*)&h[(size_t)s0 * HID + lane * 4];
        float4 v1 = *(const float4*)&h[(size_t)s1 * HID + lane * 4];
        float4 v2 = *(const float4*)&h[(size_t)s2 * HID + lane * 4];
        float4 v3 = *(const float4*)&h[(size_t)s3 * HID + lane * 4];
        a0.x += v0.x; a0.y += v0.y; a0.z += v0.z; a0.w += v0.w;
        a1.x += v1.x; a1.y += v1.y; a1.z += v1.z; a1.w += v1.w;
        a2.x += v2.x; a2.y += v2.y; a2.z += v2.z; a2.w += v2.w;
        a3.x += v3.x; a3.y += v3.y; a3.z += v3.z; a3.w += v3.w;
    }
    for (; i < end; i++) {
        float4 v0 = *(const float4*)&h[(size_t)g_srcs[i] * HID + lane * 4];
        a0.x += v0.x; a0.y += v0.y; a0.z += v0.z; a0.w += v0.w;
    }
    float inv = g_invdeg[node];
    float m0 = (a0.x + a1.x + a2.x + a3.x) * inv;
    float m1 = (a0.y + a1.y + a2.y + a3.y) * inv;
    float m2 = (a0.z + a1.z + a2.z + a3.z) * inv;
    float m3 = (a0.w + a1.w + a2.w + a3.w) * inv;
    ushort4 H;
    H.x = __half_as_ushort(__float2half(m0));
    H.y = __half_as_ushort(__float2half(m1));
    H.z = __half_as_ushort(__float2half(m2));
    H.w = __half_as_ushort(__float2half(m3));
    int tile = node >> 7, r = node & 127;
    *(ushort4*)(img + (size_t)tile * 32768 + img_off(r, lane >> 1) + (lane & 1) * 8) = H;
}

// ================= weight image prep (fp16 hi + lo) =================
__global__ void k_prepw(const float* __restrict__ W, uint8_t* __restrict__ img,
                        int K, int NOUT) {
    int idx = blockIdx.x * blockDim.x + threadIdx.x;
    if (idx >= K * NOUT) return;
    int k = idx / NOUT, n = idx % NOUT;
    float v = W[idx];
    __half hi = __float2half(v);
    __half lo = __float2half(v - __half2float(hi));
    int SUW = K >> 3;
    size_t unit = (size_t)n * SUW + ((k >> 3) ^ (n & 7));
    size_t byteo = unit * 16 + (size_t)(k & 7) * 2;
    *(__half*)(img + byteo) = hi;
    *(__half*)(img + (size_t)NOUT * K * 2 + byteo) = lo;
}

// ================= mma.sync / cp.async helpers =================
__device__ __forceinline__ uint32_t smem_u32(const void* p) {
    uint32_t a;
    asm("{ .reg .u64 t; cvta.to.shared.u64 t, %1; cvt.u32.u64 %0, t; }" : "=r"(a) : "l"(p));
    return a;
}
__device__ __forceinline__ void cp16(uint32_t dst, const void* src) {
    asm volatile("cp.async.cg.shared.global [%0], [%1], 16;" :: "r"(dst), "l"(src));
}
__device__ __forceinline__ void cp_commit_wait() {
    asm volatile("cp.async.commit_group;");
    asm volatile("cp.async.wait_group 0;");
}
__device__ __forceinline__ void ldmx4(uint32_t* r, uint32_t addr) {
    asm volatile("ldmatrix.sync.aligned.m8n8.x4.shared.b16 {%0,%1,%2,%3}, [%4];"
                 : "=r"(r[0]), "=r"(r[1]), "=r"(r[2]), "=r"(r[3]) : "r"(addr));
}
__device__ __forceinline__ void mma16816(float* c, const uint32_t* a, uint32_t b0, uint32_t b1) {
    asm volatile(
        "mma.sync.aligned.m16n8k16.row.col.f32.f16.f16.f32 "
        "{%0,%1,%2,%3}, {%4,%5,%6,%7}, {%8,%9}, {%0,%1,%2,%3};"
        : "+f"(c[0]), "+f"(c[1]), "+f"(c[2]), "+f"(c[3])
        : "r"(a[0]), "r"(a[1]), "r"(a[2]), "r"(a[3]), "r"(b0), "r"(b1));
}

// ================= HMMA GEMM, 512 threads, fp16 2-term ==================
// D = Ah*(Wh + Wl): A hi-only fp16 (err 2^-11), W 2-plane fp16 (err 2^-22).
// Warp grid 4(M) x 4(N), warp tile 32x32.
// EPI 0: tanh -> h(fp32) ; EPI 1: gelu -> x1 hi-image ; EPI 2: Euler update on h
template <int K, int NB, int EPI, bool AIMG>
__global__ void __launch_bounds__(GTHREADS, 1) k_mgemm(
    const void* __restrict__ Xin, const uint8_t* __restrict__ Wimg,
    const float* __restrict__ Bb, void* __restrict__ OUTv,
    const float* __restrict__ clr, int ntiles)
{
    constexpr int NOUT = NB * 128;
    constexpr int NCHUNK = K / 128;
    constexpr int SUW = K / 8;
    constexpr int AUNITS = 128 * 16;   // units per chunk (16B each) = 32 KB
    extern __shared__ char smem[];
    uint4* Ah = (uint4*)smem;          // AUNITS (hi only)
    uint4* Wh = Ah + AUNITS;           // NOUT*SUW units hi, then lo
    const uint32_t ah_b = smem_u32(Ah);
    const uint32_t wh_b = smem_u32(Wh);
    const uint32_t wl_b = wh_b + NOUT * SUW * 16;

    const int tid = threadIdx.x;
    const int lane = tid & 31;
    const int wid = tid >> 5;
    const int wm = wid & 3;            // 4 warps over M (32 rows each)
    const int wn = wid >> 2;           // 4 warps over N (32 cols each)
    const int r8 = lane & 7;
    const int quad = lane >> 3;
    const int g = lane >> 2;
    const int tq = lane & 3;

    for (int i = tid; i < 2 * NOUT * SUW; i += GTHREADS)
        cp16(wh_b + i * 16, (const uint4*)Wimg + i);

    float decay = 0.f;
    if (EPI == 2) decay = fmaxf(clr[0], 0.f);

    for (int tile = blockIdx.x; tile < ntiles; tile += gridDim.x) {
        const int row0 = tile * 128;
        #pragma unroll 1
        for (int nb = 0; nb < NB; nb++) {
            float acc[2][4][4];
            #pragma unroll
            for (int a = 0; a < 2; a++)
                #pragma unroll
                for (int b = 0; b < 4; b++)
                    #pragma unroll
                    for (int c = 0; c < 4; c++) acc[a][b][c] = 0.f;

            #pragma unroll 1
            for (int chunk = 0; chunk < NCHUNK; chunk++) {
                if (nb == 0) {
                    __syncthreads();
                    if (AIMG) {
                        const uint8_t* src = (const uint8_t*)Xin
                            + (size_t)tile * (NCHUNK * 32768) + (size_t)chunk * 32768;
                        #pragma unroll
                        for (int i = tid; i < AUNITS; i += GTHREADS)
                            cp16(ah_b + i * 16, src + (size_t)i * 16);
                        cp_commit_wait();
                    } else {
                        const float* X = (const float*)Xin;
                        #pragma unroll 1
                        for (int u = tid; u < AUNITS; u += GTHREADS) {
                            int r = u >> 4, ku = u & 15;
                            int gr = row0 + r;
                            float4 v0 = make_float4(0.f, 0.f, 0.f, 0.f), v1 = v0;
                            if (gr < NN) {
                                const float* xp = &X[(size_t)gr * K + chunk * 128 + ku * 8];
                                v0 = *(const float4*)xp;
                                v1 = *(const float4*)(xp + 4);
                            }
                            ushort4 H0, H1;
                            H0.x = __half_as_ushort(__float2half(v0.x));
                            H0.y = __half_as_ushort(__float2half(v0.y));
                            H0.z = __half_as_ushort(__float2half(v0.z));
                            H0.w = __half_as_ushort(__float2half(v0.w));
                            H1.x = __half_as_ushort(__float2half(v1.x));
                            H1.y = __half_as_ushort(__float2half(v1.y));
                            H1.z = __half_as_ushort(__float2half(v1.z));
                            H1.w = __half_as_ushort(__float2half(v1.w));
                            uint32_t a16 = img_off(r, ku);
                            *(ushort4*)((char*)Ah + a16) = H0;
                            *(ushort4*)((char*)Ah + a16 + 8) = H1;
                        }
                        cp_commit_wait();  // drain W copy
                    }
                    __syncthreads();
                }

                #pragma unroll
                for (int ks = 0; ks < 8; ks++) {
                    uint32_t a_hi[2][4];
                    #pragma unroll
                    for (int mt = 0; mt < 2; mt++) {
                        int row = wm * 32 + mt * 16 + r8 + (quad & 1) * 8;
                        int ku = 2 * ks + (quad >> 1);
                        ldmx4(a_hi[mt], ah_b + ((row << 4) + (ku ^ (row & 7))) * 16);
                    }
                    #pragma unroll
                    for (int nt2 = 0; nt2 < 2; nt2++) {
                        int nrow = nb * 128 + wn * 32 + nt2 * 16 + r8 + (quad >> 1) * 8;
                        int ku = chunk * 16 + 2 * ks + (quad & 1);
                        uint32_t off = ((uint32_t)nrow * SUW + (ku ^ (nrow & 7))) * 16;
                        uint32_t bh[4], bl[4];
                        ldmx4(bh, wh_b + off);
                        ldmx4(bl, wl_b + off);
                        #pragma unroll
                        for (int mt = 0; mt < 2; mt++) {
                            mma16816(acc[mt][2 * nt2 + 0], a_hi[mt], bh[0], bh[1]);
                            mma16816(acc[mt][2 * nt2 + 1], a_hi[mt], bh[2], bh[3]);
                            mma16816(acc[mt][2 * nt2 + 0], a_hi[mt], bl[0], bl[1]);
                            mma16816(acc[mt][2 * nt2 + 1], a_hi[mt], bl[2], bl[3]);
                        }
                    }
                }
            }

            // ---- epilogue: warp covers 32 rows x 32 cols ----
            #pragma unroll
            for (int mt = 0; mt < 2; mt++) {
                int rbase = row0 + wm * 32 + mt * 16 + g;
                #pragma unroll
                for (int nt = 0; nt < 4; nt++) {
                    int col = nb * 128 + wn * 32 + nt * 8 + 2 * tq;
                    float2 bb = *(const float2*)&Bb[col];
                    #pragma unroll
                    for (int half = 0; half < 2; half++) {
                        int row = rbase + half * 8;
                        if (row >= NN) continue;
                        float x0 = acc[mt][nt][2 * half + 0] + bb.x;
                        float x1 = acc[mt][nt][2 * half + 1] + bb.y;
                        if (EPI == 0) {
                            float2 o;
                            o.x = fast_tanh(x0);
                            o.y = fast_tanh(x1);
                            *(float2*)&((float*)OUTv)[(size_t)row * NOUT + col] = o;
                        } else if (EPI == 1) {
                            const float c = 0.7071067811865475f;
                            float g0 = 0.5f * x0 * (1.f + erff(x0 * c));
                            float g1 = 0.5f * x1 * (1.f + erff(x1 * c));
                            __half2 p;
                            p.x = __float2half(g0);
                            p.y = __float2half(g1);
                            int t2 = row >> 7, r = row & 127;
                            int chunk = col >> 7, kcol = col & 127;
                            *(uint32_t*)((uint8_t*)OUTv + (size_t)t2 * 65536
                                         + (size_t)chunk * 32768
                                         + img_off(r, kcol >> 3) + (kcol & 7) * 2)
                                = *(uint32_t*)&p;
                        } else {
                            float* OUT = (float*)OUTv;
                            float2 hv = *(const float2*)&OUT[(size_t)row * NOUT + col];
                            float2 o;
                            o.x = hv.x + (fast_tanh(x0) - decay * hv.x) * DTC;
                            o.y = hv.y + (fast_tanh(x1) - decay * hv.y) * DTC;
                            *(float2*)&OUT[(size_t)row * NOUT + col] = o;
                        }
                    }
                }
            }
        }
    }
}

// ================= launch =================
extern "C" void kernel_launch(void* const* d_in, const int* in_sizes, int n_in,
                              void* d_out, int out_size) {
    const float* gat  = (const float*)d_in[0];
    const int*   ei   = (const int*)d_in[1];
    const float* W_in = (const float*)d_in[2];
    const float* b_in = (const float*)d_in[3];
    const float* W1   = (const float*)d_in[4];
    const float* b1   = (const float*)d_in[5];
    const float* W2   = (const float*)d_in[6];
    const float* b2   = (const float*)d_in[7];
    const float* clr  = (const float*)d_in[8];
    float* h = (float*)d_out;

    uint8_t *aggimg = nullptr, *x1img = nullptr;
    uint8_t *wi_in = nullptr, *wi_1 = nullptr, *wi_2 = nullptr;
    cudaGetSymbolAddress((void**)&aggimg, g_aggimg);
    cudaGetSymbolAddress((void**)&x1img, g_x1img);
    cudaGetSymbolAddress((void**)&wi_in, g_Wimg_in);
    cudaGetSymbolAddress((void**)&wi_1, g_Wimg1);
    cudaGetSymbolAddress((void**)&wi_2, g_Wimg2);

    int sms = 148;
    cudaDeviceGetAttribute(&sms, cudaDevAttrMultiProcessorCount, 0);

    const int SM_IN = 32768 + 65536;    //  96 KB
    const int SM_G1 = 32768 + 131072;   // 160 KB
    const int SM_G2 = 32768 + 131072;   // 160 KB
    cudaFuncSetAttribute(k_mgemm<128, 1, 0, false>, cudaFuncAttributeMaxDynamicSharedMemorySize, SM_IN);
    cudaFuncSetAttribute(k_mgemm<128, 2, 1, true>,  cudaFuncAttributeMaxDynamicSharedMemorySize, SM_G1);
    cudaFuncSetAttribute(k_mgemm<256, 1, 2, true>,  cudaFuncAttributeMaxDynamicSharedMemorySize, SM_G2);

    const int ntiles = NTILES;
    const int grid = (ntiles < sms) ? ntiles : sms;

    // gemm0 at launch index 3 so ncu's profiled launch is the GEMM family
    k_prepw<<<(128 * 128 + 255) / 256, 256>>>(W_in, wi_in, 128, 128);       // 0
    k_zero_degi<<<(NN + 255) / 256, 256>>>();                               // 1
    k_hist<<<(NE + 255) / 256, 256>>>(ei);                                  // 2
    k_mgemm<128, 1, 0, false><<<grid, GTHREADS, SM_IN>>>(gat, wi_in, b_in,
                                                         h, clr, ntiles);   // 3
    k_scan<<<1, 1024>>>();                                                  // 4
    k_scatter<<<(NE + 255) / 256, 256>>>(ei);                               // 5
    k_prepw<<<(128 * 256 + 255) / 256, 256>>>(W1, wi_1, 128, 256);          // 6
    k_prepw<<<(256 * 128 + 255) / 256, 256>>>(W2, wi_2, 256, 128);          // 7

    const int agg_blocks = (NN * 32 + 255) / 256;
    for (int s = 0; s < STEPS; s++) {
        k_aggregate<<<agg_blocks, 256>>>(h, aggimg);
        k_mgemm<128, 2, 1, true><<<grid, GTHREADS, SM_G1>>>(aggimg, wi_1, b1, x1img, clr, ntiles);
        k_mgemm<256, 1, 2, true><<<grid, GTHREADS, SM_G2>>>(x1img, wi_2, b2, h, clr, ntiles);
    }
}

// round 13
// speedup vs baseline: 1.7907x; 1.1129x over previous
#include <cuda_runtime.h>
#include <cuda_fp16.h>
#include <math.h>
#include <stdint.h>

#define NN 50000
#define NE 800000
#define HID 128
#define HID2 256
#define STEPS 12
#define DTC 0.5f
#define NTILES 391   // ceil(NN/128)
#define GTHREADS 256

// ---- A-image layout (fp16): per 128-row tile, per 128-K chunk:
// 128 rows x 16 units; unit = 8 fp16 cols = 16B. phys unit = ku ^ (r & 7).
// Chunk = 32768 B.
__device__ __forceinline__ uint32_t img_off(int r, int ku) {
    return (((uint32_t)r << 4) + ((uint32_t)ku ^ (r & 7))) * 16u;
}

// ================= scratch =================
__device__ uint8_t g_aggimg[(size_t)NTILES * 32768];        // 12.8 MB
__device__ uint8_t g_x1img[(size_t)NTILES * 2 * 32768];     // 25.6 MB
__device__ float   g_invdeg[NN];
__device__ int     g_degi[NN];
__device__ int     g_rowptr[NN + 1];
__device__ int     g_cursor[NN];
__device__ int     g_srcs[NE];
// fp16 weight images ([N][K] units, 16B-unit XOR swizzle)
__device__ uint8_t g_Wimg_in[128 * 128 * 2];   // 32 KB
__device__ uint8_t g_Wimg1[256 * 128 * 2];     // 64 KB
__device__ uint8_t g_Wimg2[128 * 256 * 2];     // 64 KB

// ================= fast math =================
__device__ __forceinline__ float fast_tanh(float x) {
    float e = __expf(2.0f * x);
    return 1.0f - __fdividef(2.0f, e + 1.0f);
}

// ================= CSR build =================
__global__ void k_zero_degi() {
    int i = blockIdx.x * blockDim.x + threadIdx.x;
    if (i < NN) g_degi[i] = 0;
}
__global__ void k_hist(const int* __restrict__ ei) {
    int e = blockIdx.x * blockDim.x + threadIdx.x;
    if (e < NE) atomicAdd(&g_degi[ei[NE + e]], 1);
}
__global__ void k_scan() {
    __shared__ int part[1024];
    const int C = (NN + 1023) / 1024;
    int t = threadIdx.x;
    int beg = t * C, end = min(beg + C, NN);
    int s = 0;
    for (int i = beg; i < end; i++) s += g_degi[i];
    part[t] = s;
    __syncthreads();
    for (int off = 1; off < 1024; off <<= 1) {
        int v = (t >= off) ? part[t - off] : 0;
        __syncthreads();
        part[t] += v;
        __syncthreads();
    }
    int run = part[t] - s;
    for (int i = beg; i < end; i++) {
        int d = g_degi[i];
        g_rowptr[i] = run;
        g_cursor[i] = run;
        g_invdeg[i] = 1.0f / (float)max(d, 1);
        run += d;
    }
    if (t == 1023) g_rowptr[NN] = NE;
}
__global__ void k_scatter(const int* __restrict__ ei) {
    int e = blockIdx.x * blockDim.x + threadIdx.x;
    if (e < NE) {
        int dst = ei[NE + e];
        int p = atomicAdd(&g_cursor[dst], 1);
        g_srcs[p] = ei[e];
    }
}

// ================= aggregation: writes fp16 image =================
__global__ void k_aggregate(const float* __restrict__ h, uint8_t* __restrict__ img) {
    int node = (blockIdx.x * blockDim.x + threadIdx.x) >> 5;
    int lane = threadIdx.x & 31;
    if (node >= NN) return;
    int beg = g_rowptr[node], end = g_rowptr[node + 1];
    float4 a0 = make_float4(0.f, 0.f, 0.f, 0.f);
    float4 a1 = a0, a2 = a0, a3 = a0;
    int i = beg;
    for (; i + 3 < end; i += 4) {
        int s0 = g_srcs[i], s1 = g_srcs[i + 1], s2 = g_srcs[i + 2], s3 = g_srcs[i + 3];
        float4 v0 = *(const float4*)&h[(size_t)s0 * HID + lane * 4];
        float4 v1 = *(const float4*)&h[(size_t)s1 * HID + lane * 4];
        float4 v2 = *(const float4*)&h[(size_t)s2 * HID + lane * 4];
        float4 v3 = *(const float4*)&h[(size_t)s3 * HID + lane * 4];
        a0.x += v0.x; a0.y += v0.y; a0.z += v0.z; a0.w += v0.w;
        a1.x += v1.x; a1.y += v1.y; a1.z += v1.z; a1.w += v1.w;
        a2.x += v2.x; a2.y += v2.y; a2.z += v2.z; a2.w += v2.w;
        a3.x += v3.x; a3.y += v3.y; a3.z += v3.z; a3.w += v3.w;
    }
    for (; i < end; i++) {
        float4 v0 = *(const float4*)&h[(size_t)g_srcs[i] * HID + lane * 4];
        a0.x += v0.x; a0.y += v0.y; a0.z += v0.z; a0.w += v0.w;
    }
    float inv = g_invdeg[node];
    float m0 = (a0.x + a1.x + a2.x + a3.x) * inv;
    float m1 = (a0.y + a1.y + a2.y + a3.y) * inv;
    float m2 = (a0.z + a1.z + a2.z + a3.z) * inv;
    float m3 = (a0.w + a1.w + a2.w + a3.w) * inv;
    ushort4 H;
    H.x = __half_as_ushort(__float2half(m0));
    H.y = __half_as_ushort(__float2half(m1));
    H.z = __half_as_ushort(__float2half(m2));
    H.w = __half_as_ushort(__float2half(m3));
    int tile = node >> 7, r = node & 127;
    *(ushort4*)(img + (size_t)tile * 32768 + img_off(r, lane >> 1) + (lane & 1) * 8) = H;
}

// ================= weight image prep (fp16) =================
__global__ void k_prepw(const float* __restrict__ W, uint8_t* __restrict__ img,
                        int K, int NOUT) {
    int idx = blockIdx.x * blockDim.x + threadIdx.x;
    if (idx >= K * NOUT) return;
    int k = idx / NOUT, n = idx % NOUT;
    int SUW = K >> 3;
    size_t unit = (size_t)n * SUW + ((k >> 3) ^ (n & 7));
    *(__half*)(img + unit * 16 + (size_t)(k & 7) * 2) = __float2half(W[idx]);
}

// ================= mma.sync / cp.async helpers =================
__device__ __forceinline__ uint32_t smem_u32(const void* p) {
    uint32_t a;
    asm("{ .reg .u64 t; cvta.to.shared.u64 t, %1; cvt.u32.u64 %0, t; }" : "=r"(a) : "l"(p));
    return a;
}
__device__ __forceinline__ void cp16(uint32_t dst, const void* src) {
    asm volatile("cp.async.cg.shared.global [%0], [%1], 16;" :: "r"(dst), "l"(src));
}
__device__ __forceinline__ void cp_commit_wait() {
    asm volatile("cp.async.commit_group;");
    asm volatile("cp.async.wait_group 0;");
}
__device__ __forceinline__ void ldmx4(uint32_t* r, uint32_t addr) {
    asm volatile("ldmatrix.sync.aligned.m8n8.x4.shared.b16 {%0,%1,%2,%3}, [%4];"
                 : "=r"(r[0]), "=r"(r[1]), "=r"(r[2]), "=r"(r[3]) : "r"(addr));
}
__device__ __forceinline__ void mma16816(float* c, const uint32_t* a, uint32_t b0, uint32_t b1) {
    asm volatile(
        "mma.sync.aligned.m16n8k16.row.col.f32.f16.f16.f32 "
        "{%0,%1,%2,%3}, {%4,%5,%6,%7}, {%8,%9}, {%0,%1,%2,%3};"
        : "+f"(c[0]), "+f"(c[1]), "+f"(c[2]), "+f"(c[3])
        : "r"(a[0]), "r"(a[1]), "r"(a[2]), "r"(a[3]), "r"(b0), "r"(b1));
}

// ================= HMMA GEMM, 256 threads x 2 CTAs/SM, plain fp16 =========
// Warp grid 4(M) x 2(N): warp tile 32 rows x 64 cols (acc 64 regs).
// EPI 0: tanh -> h(fp32) ; EPI 1: gelu -> x1 image ; EPI 2: Euler update on h
template <int K, int NB, int EPI, bool AIMG>
__global__ void __launch_bounds__(GTHREADS, 2) k_mgemm(
    const void* __restrict__ Xin, const uint8_t* __restrict__ Wimg,
    const float* __restrict__ Bb, void* __restrict__ OUTv,
    const float* __restrict__ clr, int ntiles)
{
    constexpr int NOUT = NB * 128;
    constexpr int NCHUNK = K / 128;
    constexpr int SUW = K / 8;
    constexpr int AUNITS = 128 * 16;   // units per chunk (16B each) = 32 KB
    extern __shared__ char smem[];
    uint4* Ah = (uint4*)smem;          // AUNITS
    uint4* Wh = Ah + AUNITS;           // NOUT*SUW units
    const uint32_t ah_b = smem_u32(Ah);
    const uint32_t wh_b = smem_u32(Wh);

    const int tid = threadIdx.x;
    const int lane = tid & 31;
    const int wid = tid >> 5;
    const int wm = wid & 3;            // 4 warps over M (32 rows each)
    const int wn = wid >> 2;           // 2 warps over N (64 cols each)
    const int r8 = lane & 7;
    const int quad = lane >> 3;
    const int g = lane >> 2;
    const int tq = lane & 3;

    for (int i = tid; i < NOUT * SUW; i += GTHREADS)
        cp16(wh_b + i * 16, (const uint4*)Wimg + i);

    float decay = 0.f;
    if (EPI == 2) decay = fmaxf(clr[0], 0.f);

    for (int tile = blockIdx.x; tile < ntiles; tile += gridDim.x) {
        const int row0 = tile * 128;
        #pragma unroll 1
        for (int nb = 0; nb < NB; nb++) {
            float acc[2][8][4];
            #pragma unroll
            for (int a = 0; a < 2; a++)
                #pragma unroll
                for (int b = 0; b < 8; b++)
                    #pragma unroll
                    for (int c = 0; c < 4; c++) acc[a][b][c] = 0.f;

            #pragma unroll 1
            for (int chunk = 0; chunk < NCHUNK; chunk++) {
                if (nb == 0) {
                    __syncthreads();
                    if (AIMG) {
                        const uint8_t* src = (const uint8_t*)Xin
                            + (size_t)tile * (NCHUNK * 32768) + (size_t)chunk * 32768;
                        #pragma unroll
                        for (int i = tid; i < AUNITS; i += GTHREADS)
                            cp16(ah_b + i * 16, src + (size_t)i * 16);
                        cp_commit_wait();
                    } else {
                        const float* X = (const float*)Xin;
                        #pragma unroll 1
                        for (int u = tid; u < AUNITS; u += GTHREADS) {
                            int r = u >> 4, ku = u & 15;
                            int gr = row0 + r;
                            float4 v0 = make_float4(0.f, 0.f, 0.f, 0.f), v1 = v0;
                            if (gr < NN) {
                                const float* xp = &X[(size_t)gr * K + chunk * 128 + ku * 8];
                                v0 = *(const float4*)xp;
                                v1 = *(const float4*)(xp + 4);
                            }
                            ushort4 H0, H1;
                            H0.x = __half_as_ushort(__float2half(v0.x));
                            H0.y = __half_as_ushort(__float2half(v0.y));
                            H0.z = __half_as_ushort(__float2half(v0.z));
                            H0.w = __half_as_ushort(__float2half(v0.w));
                            H1.x = __half_as_ushort(__float2half(v1.x));
                            H1.y = __half_as_ushort(__float2half(v1.y));
                            H1.z = __half_as_ushort(__float2half(v1.z));
                            H1.w = __half_as_ushort(__float2half(v1.w));
                            uint32_t a16 = img_off(r, ku);
                            *(ushort4*)((char*)Ah + a16) = H0;
                            *(ushort4*)((char*)Ah + a16 + 8) = H1;
                        }
                        cp_commit_wait();  // drain W copy
                    }
                    __syncthreads();
                }

                #pragma unroll
                for (int ks = 0; ks < 8; ks++) {
                    uint32_t a_hi[2][4];
                    #pragma unroll
                    for (int mt = 0; mt < 2; mt++) {
                        int row = wm * 32 + mt * 16 + r8 + (quad & 1) * 8;
                        int ku = 2 * ks + (quad >> 1);
                        ldmx4(a_hi[mt], ah_b + ((row << 4) + (ku ^ (row & 7))) * 16);
                    }
                    #pragma unroll
                    for (int nt2 = 0; nt2 < 4; nt2++) {
                        int nrow = nb * 128 + wn * 64 + nt2 * 16 + r8 + (quad >> 1) * 8;
                        int ku = chunk * 16 + 2 * ks + (quad & 1);
                        uint32_t off = ((uint32_t)nrow * SUW + (ku ^ (nrow & 7))) * 16;
                        uint32_t bh[4];
                        ldmx4(bh, wh_b + off);
                        #pragma unroll
                        for (int mt = 0; mt < 2; mt++) {
                            mma16816(acc[mt][2 * nt2 + 0], a_hi[mt], bh[0], bh[1]);
                            mma16816(acc[mt][2 * nt2 + 1], a_hi[mt], bh[2], bh[3]);
                        }
                    }
                }
            }

            // ---- epilogue: warp covers 32 rows x 64 cols ----
            #pragma unroll
            for (int mt = 0; mt < 2; mt++) {
                int rbase = row0 + wm * 32 + mt * 16 + g;
                #pragma unroll
                for (int nt = 0; nt < 8; nt++) {
                    int col = nb * 128 + wn * 64 + nt * 8 + 2 * tq;
                    float2 bb = *(const float2*)&Bb[col];
                    #pragma unroll
                    for (int half = 0; half < 2; half++) {
                        int row = rbase + half * 8;
                        if (row >= NN) continue;
                        float x0 = acc[mt][nt][2 * half + 0] + bb.x;
                        float x1 = acc[mt][nt][2 * half + 1] + bb.y;
                        if (EPI == 0) {
                            float2 o;
                            o.x = fast_tanh(x0);
                            o.y = fast_tanh(x1);
                            *(float2*)&((float*)OUTv)[(size_t)row * NOUT + col] = o;
                        } else if (EPI == 1) {
                            const float c = 0.7071067811865475f;
                            float g0 = 0.5f * x0 * (1.f + erff(x0 * c));
                            float g1 = 0.5f * x1 * (1.f + erff(x1 * c));
                            __half2 p;
                            p.x = __float2half(g0);
                            p.y = __float2half(g1);
                            int t2 = row >> 7, r = row & 127;
                            int chunk = col >> 7, kcol = col & 127;
                            *(uint32_t*)((uint8_t*)OUTv + (size_t)t2 * 65536
                                         + (size_t)chunk * 32768
                                         + img_off(r, kcol >> 3) + (kcol & 7) * 2)
                                = *(uint32_t*)&p;
                        } else {
                            float* OUT = (float*)OUTv;
                            float2 hv = *(const float2*)&OUT[(size_t)row * NOUT + col];
                            float2 o;
                            o.x = hv.x + (fast_tanh(x0) - decay * hv.x) * DTC;
                            o.y = hv.y + (fast_tanh(x1) - decay * hv.y) * DTC;
                            *(float2*)&OUT[(size_t)row * NOUT + col] = o;
                        }
                    }
                }
            }
        }
    }
}

// ================= launch =================
extern "C" void kernel_launch(void* const* d_in, const int* in_sizes, int n_in,
                              void* d_out, int out_size) {
    const float* gat  = (const float*)d_in[0];
    const int*   ei   = (const int*)d_in[1];
    const float* W_in = (const float*)d_in[2];
    const float* b_in = (const float*)d_in[3];
    const float* W1   = (const float*)d_in[4];
    const float* b1   = (const float*)d_in[5];
    const float* W2   = (const float*)d_in[6];
    const float* b2   = (const float*)d_in[7];
    const float* clr  = (const float*)d_in[8];
    float* h = (float*)d_out;

    uint8_t *aggimg = nullptr, *x1img = nullptr;
    uint8_t *wi_in = nullptr, *wi_1 = nullptr, *wi_2 = nullptr;
    cudaGetSymbolAddress((void**)&aggimg, g_aggimg);
    cudaGetSymbolAddress((void**)&x1img, g_x1img);
    cudaGetSymbolAddress((void**)&wi_in, g_Wimg_in);
    cudaGetSymbolAddress((void**)&wi_1, g_Wimg1);
    cudaGetSymbolAddress((void**)&wi_2, g_Wimg2);

    int sms = 148;
    cudaDeviceGetAttribute(&sms, cudaDevAttrMultiProcessorCount, 0);

    const int SM_IN = 32768 + 32768;    // 64 KB  (A + W_in)
    const int SM_G1 = 32768 + 65536;    // 96 KB  (A + W1)
    const int SM_G2 = 32768 + 65536;    // 96 KB  (A + W2)
    cudaFuncSetAttribute(k_mgemm<128, 1, 0, false>, cudaFuncAttributeMaxDynamicSharedMemorySize, SM_IN);
    cudaFuncSetAttribute(k_mgemm<128, 2, 1, true>,  cudaFuncAttributeMaxDynamicSharedMemorySize, SM_G1);
    cudaFuncSetAttribute(k_mgemm<256, 1, 2, true>,  cudaFuncAttributeMaxDynamicSharedMemorySize, SM_G2);

    const int ntiles = NTILES;
    int grid = 2 * sms;                 // 2 CTAs per SM
    if (grid > ntiles) grid = ntiles;

    // gemm0 at launch index 3 so ncu's profiled launch is the GEMM family
    k_prepw<<<(128 * 128 + 255) / 256, 256>>>(W_in, wi_in, 128, 128);       // 0
    k_zero_degi<<<(NN + 255) / 256, 256>>>();                               // 1
    k_hist<<<(NE + 255) / 256, 256>>>(ei);                                  // 2
    k_mgemm<128, 1, 0, false><<<grid, GTHREADS, SM_IN>>>(gat, wi_in, b_in,
                                                         h, clr, ntiles);   // 3
    k_scan<<<1, 1024>>>();                                                  // 4
    k_scatter<<<(NE + 255) / 256, 256>>>(ei);                               // 5
    k_prepw<<<(128 * 256 + 255) / 256, 256>>>(W1, wi_1, 128, 256);          // 6
    k_prepw<<<(256 * 128 + 255) / 256, 256>>>(W2, wi_2, 256, 128);          // 7

    const int agg_blocks = (NN * 32 + 255) / 256;
    for (int s = 0; s < STEPS; s++) {
        k_aggregate<<<agg_blocks, 256>>>(h, aggimg);
        k_mgemm<128, 2, 1, true><<<grid, GTHREADS, SM_G1>>>(aggimg, wi_1, b1, x1img, clr, ntiles);
        k_mgemm<256, 1, 2, true><<<grid, GTHREADS, SM_G2>>>(x1img, wi_2, b2, h, clr, ntiles);
    }
}